// round 1
// baseline (speedup 1.0000x reference)
#include <cuda_runtime.h>
#include <math.h>

#define BB 1024
#define SS 256
#define DD 128
#define HH 512
#define GG 2048          // 4H
#define KPAD 784         // 128 (x_c) + 512 (h) + 128 (m) + 1 (d) padded to 784
#define NIMP (1024*256*128)

typedef unsigned long long ull;

// ---------------- device scratch (no allocations allowed) ----------------
__device__ float g_A[BB*KPAD];        // per-step GEMM input [b, k]
__device__ float g_h[BB*HH];
__device__ float g_c[BB*HH];
__device__ float g_WcatT[KPAD*GG];    // [k][gcol], gcol = 4*j + gate (interleaved)
__device__ float g_biasI[GG];         // bih+bhh, interleaved layout
__device__ float g_Bc[(HH+DD)*DD];    // rows 0..511 = WhrT, rows 512..639 = WfrT
__device__ float g_loss[SS];
__device__ float g_msum[SS];

// ---------------- packed f32x2 helpers (Blackwell) ----------------
__device__ __forceinline__ ull pack2(float lo, float hi){
    ull r; asm("mov.b64 %0, {%1,%2};" : "=l"(r) : "f"(lo), "f"(hi)); return r;
}
__device__ __forceinline__ void unpack2(ull v, float &lo, float &hi){
    asm("mov.b64 {%0,%1}, %2;" : "=f"(lo), "=f"(hi) : "l"(v));
}
__device__ __forceinline__ ull ffma2(ull a, ull b, ull c){
    ull d; asm("fma.rn.f32x2 %0, %1, %2, %3;" : "=l"(d) : "l"(a), "l"(b), "l"(c)); return d;
}
__device__ __forceinline__ float sigmoidf_(float x){ return 1.f/(1.f+expf(-x)); }

__device__ __forceinline__ float block_reduce_sum(float v, float* red){
    int tid = threadIdx.x;
    red[tid] = v; __syncthreads();
    #pragma unroll
    for (int off = 128; off > 0; off >>= 1){
        if (tid < off) red[tid] += red[tid+off];
        __syncthreads();
    }
    return red[0];
}

// ---------------- init: zero state ----------------
__global__ void init_kernel(){
    int stride = gridDim.x*blockDim.x;
    int t = blockIdx.x*blockDim.x + threadIdx.x;
    for (int i=t;i<BB*KPAD;i+=stride) g_A[i]=0.f;
    for (int i=t;i<BB*HH;i+=stride){ g_h[i]=0.f; g_c[i]=0.f; }
    if (t < SS) g_loss[t]=0.f;
}

// ---------------- build packed weights ----------------
__global__ void build_kernel(const float* __restrict__ Wih, const float* __restrict__ Whh,
                             const float* __restrict__ bih, const float* __restrict__ bhh,
                             const float* __restrict__ Whr, const float* __restrict__ Wfr){
    int stride = gridDim.x*blockDim.x;
    int t0 = blockIdx.x*blockDim.x + threadIdx.x;
    const int IN = 2*DD + 1;  // 257
    for (int idx=t0; idx<KPAD*GG; idx+=stride){
        int k = idx >> 11;         // /2048
        int gcol = idx & 2047;
        int j = gcol >> 2, gate = gcol & 3;
        int gs = gate*HH + j;      // source row in Wih/Whh (i,f,g,o chunks)
        float v;
        if (k < DD)            v = Wih[gs*IN + k];                 // x_c part
        else if (k < DD+HH)    v = Whh[gs*HH + (k-DD)];            // h part
        else if (k < 2*DD+HH)  v = Wih[gs*IN + DD + (k-DD-HH)];    // m part
        else if (k == 2*DD+HH) v = Wih[gs*IN + 2*DD];              // d part
        else                   v = 0.f;                            // pad
        g_WcatT[idx] = v;
    }
    for (int gcol=t0; gcol<GG; gcol+=stride){
        int j = gcol>>2, gate = gcol&3; int gs = gate*HH + j;
        g_biasI[gcol] = bih[gs] + bhh[gs];
    }
    for (int idx=t0; idx<(HH+DD)*DD; idx+=stride){
        int k = idx >> 7, n = idx & (DD-1);
        g_Bc[idx] = (k < HH) ? Whr[n*HH + k] : Wfr[n*DD + (k-HH)];
    }
}

// ---------------- per-step mask sums ----------------
__global__ void msum_kernel(const float* __restrict__ masks){
    __shared__ float red[256];
    int s = blockIdx.x;
    float sum = 0.f;
    for (int idx = threadIdx.x; idx < BB*DD; idx += 256){
        int b = idx >> 7, d = idx & (DD-1);
        sum += masks[(size_t)b*SS*DD + (size_t)s*DD + d];
    }
    float tot = block_reduce_sum(sum, red);
    if (threadIdx.x == 0) g_msum[s] = tot;
}

// ---------------- step A: decay h, x_h GEMM, build A ----------------
// grid: 64 blocks (16 rows each), 256 threads; C tile [16 x 128], K = 512
__global__ __launch_bounds__(256,1) void prepA_kernel(
    const float* __restrict__ data, const float* __restrict__ masks,
    const float* __restrict__ deltas, const float* __restrict__ Wtd,
    const float* __restrict__ btd, const float* __restrict__ bhr, int s)
{
    __shared__ float As[16][17];
    __shared__ float Bs[16][132];
    int tid = threadIdx.x;
    int m0 = blockIdx.x * 16;
    int lr = tid >> 4;      // row (0..15) for both load and compute
    int lk = tid & 15;      // k within tile for load
    int tx = tid & 15;      // col group for compute
    int ty = lr;
    float d_b = deltas[(size_t)(m0 + lr)*SS + s];

    ull acc[4] = {0ull,0ull,0ull,0ull};
    for (int k0 = 0; k0 < HH; k0 += 16){
        int k = k0 + lk;
        float hv  = g_h[(size_t)(m0+lr)*HH + k];
        float td  = d_b * Wtd[k] + btd[k];
        float dec = expf(-fmaxf(td, 0.f));
        float hd  = hv * dec;
        As[lk][lr] = hd;
        g_A[(size_t)(m0+lr)*KPAD + DD + k] = hd;   // hdec region of A
        #pragma unroll
        for (int i=0;i<2;i++){
            int idx = i*256 + tid;
            int kk = idx >> 5; int n4 = (idx & 31) << 2;
            *(float4*)&Bs[kk][n4] = *(const float4*)&g_Bc[(size_t)(k0+kk)*DD + n4];
        }
        __syncthreads();
        #pragma unroll
        for (int kk=0; kk<16; kk++){
            float a = As[kk][ty];
            ull a2 = pack2(a, a);
            float4 b01 = *(float4*)&Bs[kk][tx*8];
            float4 b23 = *(float4*)&Bs[kk][tx*8+4];
            acc[0]=ffma2(a2, pack2(b01.x,b01.y), acc[0]);
            acc[1]=ffma2(a2, pack2(b01.z,b01.w), acc[1]);
            acc[2]=ffma2(a2, pack2(b23.x,b23.y), acc[2]);
            acc[3]=ffma2(a2, pack2(b23.z,b23.w), acc[3]);
        }
        __syncthreads();
    }
    int b = m0 + ty;
    const float* xrow = data  + (size_t)b*SS*DD + (size_t)s*DD;
    const float* mrow = masks + (size_t)b*SS*DD + (size_t)s*DD;
    float r[8];
    unpack2(acc[0], r[0], r[1]); unpack2(acc[1], r[2], r[3]);
    unpack2(acc[2], r[4], r[5]); unpack2(acc[3], r[6], r[7]);
    #pragma unroll
    for (int j=0;j<8;j++){
        int n = tx*8 + j;
        float xh = r[j] + bhr[n];
        float x  = xrow[n];
        float m  = mrow[n];
        float xc = m*x + (1.f-m)*xh;
        g_A[(size_t)b*KPAD + n] = xc;
        g_A[(size_t)b*KPAD + DD + HH + n] = m;
    }
    if (tx == 0) g_A[(size_t)b*KPAD + 2*DD + HH] = d_b;
}

// ---------------- gates GEMM + fused LSTM ----------------
// grid: (16, 8), 256 threads; C tile [128 x 128], K = 784
__global__ __launch_bounds__(256,1) void gates_kernel()
{
    __shared__ float As[16][132];
    __shared__ float Bs[16][132];
    int tid = threadIdx.x;
    int tx = tid & 15;
    int ty = tid >> 4;
    int row0 = blockIdx.y * 128;
    int col0 = blockIdx.x * 128;

    ull acc[8][4];
    #pragma unroll
    for (int i=0;i<8;i++)
        #pragma unroll
        for (int j=0;j<4;j++) acc[i][j] = 0ull;

    for (int k0 = 0; k0 < KPAD; k0 += 16){
        #pragma unroll
        for (int i=0;i<2;i++){
            int idx = i*256 + tid;           // 0..511
            int m = idx >> 2;                // 0..127
            int k4 = (idx & 3) << 2;         // 0,4,8,12
            float4 v = *(const float4*)(g_A + (size_t)(row0+m)*KPAD + k0 + k4);
            As[k4+0][m]=v.x; As[k4+1][m]=v.y; As[k4+2][m]=v.z; As[k4+3][m]=v.w;
        }
        #pragma unroll
        for (int i=0;i<2;i++){
            int idx = i*256 + tid;
            int kk = idx >> 5; int n4 = (idx & 31) << 2;
            *(float4*)&Bs[kk][n4] = *(const float4*)(g_WcatT + (size_t)(k0+kk)*GG + col0 + n4);
        }
        __syncthreads();
        #pragma unroll
        for (int kk=0; kk<16; kk++){
            float a[8];
            *(float4*)&a[0] = *(float4*)&As[kk][ty*8];
            *(float4*)&a[4] = *(float4*)&As[kk][ty*8+4];
            float4 b01 = *(float4*)&Bs[kk][tx*8];
            float4 b23 = *(float4*)&Bs[kk][tx*8+4];
            ull b[4];
            b[0]=pack2(b01.x,b01.y); b[1]=pack2(b01.z,b01.w);
            b[2]=pack2(b23.x,b23.y); b[3]=pack2(b23.z,b23.w);
            #pragma unroll
            for (int i=0;i<8;i++){
                ull a2 = pack2(a[i], a[i]);
                #pragma unroll
                for (int j=0;j<4;j++) acc[i][j] = ffma2(a2, b[j], acc[i][j]);
            }
        }
        __syncthreads();
    }

    // fused LSTM epilogue: cols col0+tx*8 .. +7 = gates (i,f,g,o) of h-indices j0, j0+1
    int cbase = col0 + tx*8;
    int j0 = cbase >> 2;
    float bb[8];
    *(float4*)&bb[0] = *(const float4*)&g_biasI[cbase];
    *(float4*)&bb[4] = *(const float4*)&g_biasI[cbase+4];
    #pragma unroll
    for (int i=0;i<8;i++){
        int b = row0 + ty*8 + i;
        float r[8];
        unpack2(acc[i][0], r[0], r[1]); unpack2(acc[i][1], r[2], r[3]);
        unpack2(acc[i][2], r[4], r[5]); unpack2(acc[i][3], r[6], r[7]);
        #pragma unroll
        for (int q=0;q<8;q++) r[q] += bb[q];
        {
            int j = j0;
            float cold = g_c[(size_t)b*HH + j];
            float cn = sigmoidf_(r[1])*cold + sigmoidf_(r[0])*tanhf(r[2]);
            g_c[(size_t)b*HH + j] = cn;
            g_h[(size_t)b*HH + j] = sigmoidf_(r[3])*tanhf(cn);
        }
        {
            int j = j0 + 1;
            float cold = g_c[(size_t)b*HH + j];
            float cn = sigmoidf_(r[5])*cold + sigmoidf_(r[4])*tanhf(r[6]);
            g_c[(size_t)b*HH + j] = cn;
            g_h[(size_t)b*HH + j] = sigmoidf_(r[7])*tanhf(cn);
        }
    }
}

// ---------------- step C: x_h2 & x_f GEMM, outputs, loss ----------------
// grid: 64 blocks, 256 threads; C tile [16 x 128], K = 640 (512 h + 128 x)
__global__ __launch_bounds__(256,1) void stepC_kernel(
    const float* __restrict__ data, const float* __restrict__ masks,
    const float* __restrict__ bhr, const float* __restrict__ bfr,
    float* __restrict__ out, int s)
{
    __shared__ float As[16][17];
    __shared__ float Bs[16][132];
    __shared__ float red[256];
    int tid = threadIdx.x;
    int m0 = blockIdx.x * 16;
    int lr = tid >> 4;
    int lk = tid & 15;
    int tx = tid & 15;
    int ty = lr;

    ull accH[4] = {0ull,0ull,0ull,0ull};
    ull accX[4] = {0ull,0ull,0ull,0ull};

    // part 1: h_new @ WhrT  (k in [0,512))
    for (int k0 = 0; k0 < HH; k0 += 16){
        int k = k0 + lk;
        As[lk][lr] = g_h[(size_t)(m0+lr)*HH + k];
        #pragma unroll
        for (int i=0;i<2;i++){
            int idx = i*256 + tid;
            int kk = idx >> 5; int n4 = (idx & 31) << 2;
            *(float4*)&Bs[kk][n4] = *(const float4*)&g_Bc[(size_t)(k0+kk)*DD + n4];
        }
        __syncthreads();
        #pragma unroll
        for (int kk=0; kk<16; kk++){
            float a = As[kk][ty];
            ull a2 = pack2(a, a);
            float4 b01 = *(float4*)&Bs[kk][tx*8];
            float4 b23 = *(float4*)&Bs[kk][tx*8+4];
            accH[0]=ffma2(a2, pack2(b01.x,b01.y), accH[0]);
            accH[1]=ffma2(a2, pack2(b01.z,b01.w), accH[1]);
            accH[2]=ffma2(a2, pack2(b23.x,b23.y), accH[2]);
            accH[3]=ffma2(a2, pack2(b23.z,b23.w), accH[3]);
        }
        __syncthreads();
    }
    // part 2: x @ WfrT  (k in [512,640))
    for (int k0 = HH; k0 < HH+DD; k0 += 16){
        int k = k0 + lk;
        As[lk][lr] = data[(size_t)(m0+lr)*SS*DD + (size_t)s*DD + (k - HH)];
        #pragma unroll
        for (int i=0;i<2;i++){
            int idx = i*256 + tid;
            int kk = idx >> 5; int n4 = (idx & 31) << 2;
            *(float4*)&Bs[kk][n4] = *(const float4*)&g_Bc[(size_t)(k0+kk)*DD + n4];
        }
        __syncthreads();
        #pragma unroll
        for (int kk=0; kk<16; kk++){
            float a = As[kk][ty];
            ull a2 = pack2(a, a);
            float4 b01 = *(float4*)&Bs[kk][tx*8];
            float4 b23 = *(float4*)&Bs[kk][tx*8+4];
            accX[0]=ffma2(a2, pack2(b01.x,b01.y), accX[0]);
            accX[1]=ffma2(a2, pack2(b01.z,b01.w), accX[1]);
            accX[2]=ffma2(a2, pack2(b23.x,b23.y), accX[2]);
            accX[3]=ffma2(a2, pack2(b23.z,b23.w), accX[3]);
        }
        __syncthreads();
    }

    int b = m0 + ty;
    const float* xrow = data  + (size_t)b*SS*DD + (size_t)s*DD;
    const float* mrow = masks + (size_t)b*SS*DD + (size_t)s*DD;
    float rh[8], rx[8];
    unpack2(accH[0], rh[0], rh[1]); unpack2(accH[1], rh[2], rh[3]);
    unpack2(accH[2], rh[4], rh[5]); unpack2(accH[3], rh[6], rh[7]);
    unpack2(accX[0], rx[0], rx[1]); unpack2(accX[1], rx[2], rx[3]);
    unpack2(accX[2], rx[4], rx[5]); unpack2(accX[3], rx[6], rx[7]);
    float lsum = 0.f;
    #pragma unroll
    for (int j=0;j<8;j++){
        int n = tx*8 + j;
        float xh2 = rh[j] + bhr[n];
        float xf  = rx[j] + bfr[n];
        float x   = xrow[n];
        float m   = mrow[n];
        out[(size_t)b*SS*DD + (size_t)s*DD + n] = m*x + (1.f-m)*(xh2 + xf);
        float e = x - xh2;
        lsum += e*e*m;
    }
    float tot = block_reduce_sum(lsum, red);
    if (tid == 0) atomicAdd(&g_loss[s], tot);
}

// ---------------- final loss ----------------
__global__ void final_kernel(float* __restrict__ out, int out_size){
    __shared__ float red[256];
    int s = threadIdx.x;
    float v = g_loss[s] / (g_msum[s] + 1e-5f);
    float tot = block_reduce_sum(v, red);
    if (s == 0 && out_size > NIMP) out[NIMP] = tot / (float)SS;
}

// ---------------- launch ----------------
extern "C" void kernel_launch(void* const* d_in, const int* in_sizes, int n_in,
                              void* d_out, int out_size){
    const float* data   = (const float*)d_in[0];
    const float* masks  = (const float*)d_in[1];
    const float* deltas = (const float*)d_in[2];
    const float* Wih    = (const float*)d_in[3];
    const float* Whh    = (const float*)d_in[4];
    const float* bih    = (const float*)d_in[5];
    const float* bhh    = (const float*)d_in[6];
    const float* Wtd    = (const float*)d_in[7];
    const float* btd    = (const float*)d_in[8];
    const float* Whr    = (const float*)d_in[9];
    const float* bhr    = (const float*)d_in[10];
    const float* Wfr    = (const float*)d_in[11];
    const float* bfr    = (const float*)d_in[12];
    float* out = (float*)d_out;

    init_kernel<<<512, 256>>>();
    build_kernel<<<512, 256>>>(Wih, Whh, bih, bhh, Whr, Wfr);
    msum_kernel<<<SS, 256>>>(masks);
    for (int s = 0; s < SS; s++){
        prepA_kernel<<<BB/16, 256>>>(data, masks, deltas, Wtd, btd, bhr, s);
        gates_kernel<<<dim3(GG/128, BB/128), 256>>>();
        stepC_kernel<<<BB/16, 256>>>(data, masks, bhr, bfr, out, s);
    }
    final_kernel<<<1, 256>>>(out, out_size);
}